// round 17
// baseline (speedup 1.0000x reference)
#include <cuda_runtime.h>
#include <cuda_fp16.h>
#include <math.h>
#include <stdint.h>

// Problem constants
#define N_NODES 16384
#define DIM     128
#define E_MAX   524288
#define ALPHA   0.2f
#define CAP     96        // per-node bucket capacity (Poisson(32) max deg ~60)

// ---------------- scratch (static device globals; no allocation) ----------------
__device__ __half  g_nbrh[N_NODES * DIM];  // nbr features (post-MLP), fp16 gather table
__device__ float   g_anbr[N_NODES];        // nbr . wa_bot (fp32)
__device__ __half  g_Wh[DIM * DIM];        // Wn^T as fp16, layout [n][k]
__device__ float   g_bn[DIM];              // b1n @ W2n + b2n
__device__ float   g_vc[DIM];              // W1c @ (W2c @ wa_top)
__device__ float   g_cconst[1];            // (b1c@W2c+b2c).wa_top + ba
__device__ int     g_counts[N_NODES];      // BSS zero-init; re-zeroed by agg each run
__device__ int     g_bktd[(size_t)N_NODES * CAP];   // dst per edge

// ---------------- helpers ----------------
__device__ __forceinline__ void mma_f16(float* c, const uint32_t* a, uint32_t b0, uint32_t b1) {
    asm volatile(
        "mma.sync.aligned.m16n8k16.row.col.f32.f16.f16.f32 "
        "{%0,%1,%2,%3}, {%4,%5,%6,%7}, {%8,%9}, {%0,%1,%2,%3};"
        : "+f"(c[0]), "+f"(c[1]), "+f"(c[2]), "+f"(c[3])
        : "r"(a[0]), "r"(a[1]), "r"(a[2]), "r"(a[3]), "r"(b0), "r"(b1));
}

// ---------------- kernels ----------------

// Launch 1 (fused): blocks 0..127 -> Wn row (4-way k-split, 512 thr);
// 128 -> bn; 129 -> vc/cconst (all phases 4-way k-split);
// blocks 130.. -> edge scatter (counts were zeroed by previous agg / BSS init).
__global__ __launch_bounds__(512) void prep_scatter_kernel(
        const float* __restrict__ W1c, const float* __restrict__ b1c,
        const float* __restrict__ W2c, const float* __restrict__ b2c,
        const float* __restrict__ W1n, const float* __restrict__ b1n,
        const float* __restrict__ W2n, const float* __restrict__ b2n,
        const float* __restrict__ Wa,  const float* __restrict__ ba,
        const int* __restrict__ edges, int E) {
    int bid = blockIdx.x;
    int t = threadIdx.x;   // 512
    if (bid >= 130) {
        // ---- scatter path: 2 edges/thread via int4 ----
        int i = (bid - 130) * 512 + t;
        int e0 = 2 * i;
        if (e0 >= E) return;
        int4 ed = ((const int4*)edges)[i];
        int p0 = atomicAdd(&g_counts[ed.x], 1);
        if (p0 < CAP) g_bktd[(size_t)ed.x * CAP + p0] = ed.y;
        if (e0 + 1 < E) {
            int p1 = atomicAdd(&g_counts[ed.z], 1);
            if (p1 < CAP) g_bktd[(size_t)ed.z * CAP + p1] = ed.w;
        }
        return;
    }

    __shared__ float row[DIM];
    __shared__ float part[4][DIM];
    __shared__ float tvec[DIM];
    __shared__ float u[DIM];
    int col = t & 127, kh = t >> 7;   // kh in 0..3, 32 k's each

    if (bid < DIM) {
        // Wn row `bid`: g_Wh[col][bid] = sum_k W1n[bid][k] * W2n[k][col]
        if (t < DIM) row[t] = W1n[bid * DIM + t];
        __syncthreads();
        float s = 0.0f;
        #pragma unroll 8
        for (int k = kh * 32; k < kh * 32 + 32; k++) s += row[k] * W2n[k * DIM + col];
        part[kh][col] = s;
        __syncthreads();
        if (kh == 0) {
            float v = (part[0][col] + part[1][col]) + (part[2][col] + part[3][col]);
            g_Wh[col * DIM + bid] = __float2half_rn(v);   // transposed [n][k]
        }
    } else if (bid == DIM) {
        float s = 0.0f;
        #pragma unroll 8
        for (int k = kh * 32; k < kh * 32 + 32; k++) s += b1n[k] * W2n[k * DIM + col];
        part[kh][col] = s;
        __syncthreads();
        if (kh == 0)
            g_bn[col] = b2n[col] + (part[0][col] + part[1][col]) + (part[2][col] + part[3][col]);
    } else {
        // vc & cconst, every phase 4-way split
        float s = 0.0f;
        #pragma unroll 8
        for (int j = kh * 32; j < kh * 32 + 32; j++) s += W2c[col * DIM + j] * Wa[j];
        part[kh][col] = s;
        __syncthreads();
        if (kh == 0) tvec[col] = (part[0][col] + part[1][col]) + (part[2][col] + part[3][col]);
        __syncthreads();
        float su = 0.0f;
        #pragma unroll 8
        for (int k = kh * 32; k < kh * 32 + 32; k++) su += b1c[k] * W2c[k * DIM + col];
        part[kh][col] = su;
        __syncthreads();
        if (kh == 0) u[col] = b2c[col] + (part[0][col] + part[1][col]) + (part[2][col] + part[3][col]);
        __syncthreads();
        float v = 0.0f;
        #pragma unroll 8
        for (int k = kh * 32; k < kh * 32 + 32; k++) v += W1c[col * DIM + k] * tvec[k];
        part[kh][col] = v;
        __syncthreads();
        if (kh == 0) g_vc[col] = (part[0][col] + part[1][col]) + (part[2][col] + part[3][col]);
        __syncthreads();
        if (t < DIM) part[0][t] = u[t] * Wa[t];
        __syncthreads();
        if (t == 0) {
            float c = ba[0];
            for (int j = 0; j < DIM; j++) c += part[0][j];
            g_cconst[0] = c;
        }
    }
}

// fp16 tensor-core GEMM: g_nbrh = fp16(X @ Wn + bn), g_anbr = row-dots (fp32).
// m16n8k16 single-term, fp32 acc. Full A tile + full B in 51KB dynamic smem,
// ONE sync, uninterrupted MMA stream. 256 blocks x 64-row tiles; 8 warps 4(m)x2(n).
#define AS 68
__global__ __launch_bounds__(256) void gemm_tc_kernel(const float* __restrict__ X,
                                                      const float* __restrict__ Wa) {
    extern __shared__ uint32_t sm[];
    uint32_t* Ah = sm;                 // [64][68] half2 pairs
    uint32_t* Bh = sm + 64 * AS;       // [128][68]
    int tid = threadIdx.x;
    int lane = tid & 31, wid = tid >> 5;
    int gid = lane >> 2, tig = lane & 3;
    int wm = wid & 3, wn = wid >> 2;
    int m0 = blockIdx.x * 64;

    const uint4* gWh4 = (const uint4*)g_Wh;   // [128][16 uint4]

    #pragma unroll
    for (int i = 0; i < 8; i++) {
        int idx = tid + i * 256;               // 0..2047
        int r = idx >> 5, c4 = (idx & 31) * 4;
        float4 v = *(const float4*)&X[(size_t)(m0 + r) * DIM + c4];
        int j = c4 >> 1;
        __half2 p0 = __floats2half2_rn(v.x, v.y);
        __half2 p1 = __floats2half2_rn(v.z, v.w);
        Ah[r * AS + j]     = *(uint32_t*)&p0;
        Ah[r * AS + j + 1] = *(uint32_t*)&p1;
    }
    #pragma unroll
    for (int i = 0; i < 8; i++) {
        int idx = tid + i * 256;               // 0..2047
        int n = idx >> 4, q = idx & 15;
        *(uint4*)&Bh[n * AS + q * 4] = gWh4[n * 16 + q];
    }
    __syncthreads();

    float acc[8][4] = {};
    int r0 = wm * 16 + gid;
    #pragma unroll
    for (int kk = 0; kk < 8; kk++) {
        int kb = kk * 8;
        uint32_t ah[4];
        ah[0] = Ah[r0 * AS + kb + tig];       ah[1] = Ah[(r0 + 8) * AS + kb + tig];
        ah[2] = Ah[r0 * AS + kb + tig + 4];   ah[3] = Ah[(r0 + 8) * AS + kb + tig + 4];
        #pragma unroll
        for (int nt = 0; nt < 8; nt++) {
            int n = wn * 64 + nt * 8 + gid;
            uint32_t b0 = Bh[n * AS + kb + tig], b1 = Bh[n * AS + kb + tig + 4];
            mma_f16(acc[nt], ah, b0, b1);
        }
    }
    __syncthreads();

    float* red = (float*)sm;
    int rl0 = wm * 16 + gid;
    int rl1 = rl0 + 8;
    int row0 = m0 + rl0, row1 = m0 + rl1;
    float ad0 = 0.0f, ad1 = 0.0f;
    #pragma unroll
    for (int nt = 0; nt < 8; nt++) {
        int col = wn * 64 + nt * 8 + tig * 2;
        float b0 = g_bn[col], b1 = g_bn[col + 1];
        float w0 = Wa[DIM + col], w1 = Wa[DIM + col + 1];
        float v0 = acc[nt][0] + b0, v1 = acc[nt][1] + b1;
        float v2 = acc[nt][2] + b0, v3 = acc[nt][3] + b1;
        *(__half2*)&g_nbrh[(size_t)row0 * DIM + col] = __floats2half2_rn(v0, v1);
        *(__half2*)&g_nbrh[(size_t)row1 * DIM + col] = __floats2half2_rn(v2, v3);
        ad0 += v0 * w0 + v1 * w1;
        ad1 += v2 * w0 + v3 * w1;
    }
    ad0 += __shfl_xor_sync(0xFFFFFFFFu, ad0, 1);
    ad0 += __shfl_xor_sync(0xFFFFFFFFu, ad0, 2);
    ad1 += __shfl_xor_sync(0xFFFFFFFFu, ad1, 1);
    ad1 += __shfl_xor_sync(0xFFFFFFFFu, ad1, 2);
    if (tig == 0) {
        red[wn * 64 + rl0] = ad0;
        red[wn * 64 + rl1] = ad1;
    }
    __syncthreads();
    if (tid < 64) g_anbr[m0 + tid] = red[tid] + red[64 + tid];
}
#define GEMM_SMEM ((64 * AS + 128 * AS) * 4)

// one warp per node; computes acur[node] inline, then two 16-lane halves
// gather different edges (LDG.128 each); w = exp(leaky(acur + anbr[dst])).
// Re-zeroes g_counts[node] after reading (invariant for next graph replay).
__global__ __launch_bounds__(256) void agg_kernel(const float* __restrict__ Xc,
                                                  float* __restrict__ out) {
    int node = blockIdx.x * 8 + (threadIdx.x >> 5);
    int lane = threadIdx.x & 31;
    int half = lane >> 4, li = lane & 15;
    if (node >= N_NODES) return;
    float4 xr = ((const float4*)(Xc + (size_t)node * DIM))[lane];
    float4 vv = ((const float4*)g_vc)[lane];
    float acn = xr.x * vv.x + xr.y * vv.y + xr.z * vv.z + xr.w * vv.w;
    int c = g_counts[node];
    if (lane == 0) g_counts[node] = 0;   // reset for next run
    if (c > CAP) c = CAP;
    const int* bkt = g_bktd + (size_t)node * CAP;
    #pragma unroll
    for (int o = 16; o; o >>= 1) acn += __shfl_xor_sync(0xFFFFFFFFu, acn, o);
    acn += g_cconst[0];

    float acc[8] = {};
    float ssum = 0.0f;
    int p = 0;
    for (; p + 16 <= c; p += 16) {
        int4 b[4];
        #pragma unroll
        for (int k = 0; k < 4; k++) b[k] = ((const int4*)(bkt + p))[k];
        int dd[8];
        #pragma unroll
        for (int j = 0; j < 8; j++) {
            int4 bb = b[j >> 1];
            dd[j] = (j & 1) ? (half ? bb.w : bb.z) : (half ? bb.y : bb.x);
        }
        uint4 u[8];
        #pragma unroll
        for (int j = 0; j < 8; j++) u[j] = ((const uint4*)(g_nbrh + (size_t)dd[j] * DIM))[li];
        float an[8];
        #pragma unroll
        for (int j = 0; j < 8; j++) an[j] = g_anbr[dd[j]];
        #pragma unroll
        for (int j = 0; j < 8; j++) {
            float sc = acn + an[j];
            sc = sc > 0.0f ? sc : ALPHA * sc;
            float w = __expf(sc);
            ssum += w;
            float2 f0 = __half22float2(*(__half2*)&u[j].x);
            float2 f1 = __half22float2(*(__half2*)&u[j].y);
            float2 f2 = __half22float2(*(__half2*)&u[j].z);
            float2 f3 = __half22float2(*(__half2*)&u[j].w);
            acc[0] += w * f0.x; acc[1] += w * f0.y;
            acc[2] += w * f1.x; acc[3] += w * f1.y;
            acc[4] += w * f2.x; acc[5] += w * f2.y;
            acc[6] += w * f3.x; acc[7] += w * f3.y;
        }
    }
    for (; p < c; p += 2) {
        int e = p + half;
        bool act = e < c;
        int d = act ? bkt[e] : 0;
        uint4 u = ((const uint4*)(g_nbrh + (size_t)d * DIM))[li];
        float w = 0.0f;
        if (act) {
            float sc = acn + g_anbr[d];
            sc = sc > 0.0f ? sc : ALPHA * sc;
            w = __expf(sc);
        }
        ssum += w;
        float2 f0 = __half22float2(*(__half2*)&u.x);
        float2 f1 = __half22float2(*(__half2*)&u.y);
        float2 f2 = __half22float2(*(__half2*)&u.z);
        float2 f3 = __half22float2(*(__half2*)&u.w);
        acc[0] += w * f0.x; acc[1] += w * f0.y;
        acc[2] += w * f1.x; acc[3] += w * f1.y;
        acc[4] += w * f2.x; acc[5] += w * f2.y;
        acc[6] += w * f3.x; acc[7] += w * f3.y;
    }
    ssum += __shfl_xor_sync(0xFFFFFFFFu, ssum, 16);
    #pragma unroll
    for (int k = 0; k < 8; k++) acc[k] += __shfl_xor_sync(0xFFFFFFFFu, acc[k], 16);
    if (half == 0) {
        float inv = 1.0f / ssum;
        float* dst = out + (size_t)node * DIM + li * 8;
        ((float4*)dst)[0] = make_float4(acc[0] * inv, acc[1] * inv, acc[2] * inv, acc[3] * inv);
        ((float4*)dst)[1] = make_float4(acc[4] * inv, acc[5] * inv, acc[6] * inv, acc[7] * inv);
    }
}

// ---------------- launch ----------------
extern "C" void kernel_launch(void* const* d_in, const int* in_sizes, int n_in,
                              void* d_out, int out_size) {
    const float* x_cur = (const float*)d_in[0];
    const float* x_nbr = (const float*)d_in[1];
    const float* W1c   = (const float*)d_in[2];
    const float* b1c   = (const float*)d_in[3];
    const float* W2c   = (const float*)d_in[4];
    const float* b2c   = (const float*)d_in[5];
    const float* W1n   = (const float*)d_in[6];
    const float* b1n   = (const float*)d_in[7];
    const float* W2n   = (const float*)d_in[8];
    const float* b2n   = (const float*)d_in[9];
    const float* Wa    = (const float*)d_in[10];
    const float* ba    = (const float*)d_in[11];
    const int*   edges = (const int*)d_in[12];
    float* out = (float*)d_out;

    int E = in_sizes[12] / 2;
    if (E > E_MAX) E = E_MAX;

    static bool attr_set = false;
    if (!attr_set) {
        cudaFuncSetAttribute(gemm_tc_kernel,
                             cudaFuncAttributeMaxDynamicSharedMemorySize, GEMM_SMEM);
        attr_set = true;
    }

    int scatter_blocks = (E / 2 + 511) / 512;
    prep_scatter_kernel<<<130 + scatter_blocks, 512>>>(
        W1c, b1c, W2c, b2c, W1n, b1n, W2n, b2n, Wa, ba, edges, E);         // 1
    gemm_tc_kernel<<<N_NODES / 64, 256, GEMM_SMEM>>>(x_nbr, Wa);           // 2
    agg_kernel<<<N_NODES / 8, 256>>>(x_cur, out);                          // 3
}